// round 2
// baseline (speedup 1.0000x reference)
#include <cuda_runtime.h>

// Problem constants (fixed by reference setup_inputs)
#define B 8
#define N 256
#define D 128
#define D4 (D / 4)          // 32 float4 per feature row

// Scratch for per-batch feature sums S[b][d] (alloc-free rule: __device__ global)
__device__ float4 g_sum[B * D4];

// Kernel 1: S[b, :] = sum_n x[b, n, :]
// Grid: B blocks, 256 threads. Thread t = g*32 + d4 (g in 0..7 node-group, d4 in 0..31).
// Each thread sums 32 nodes of one float4 column, then smem-reduce the 8 groups.
__global__ void reduce_kernel(const float4* __restrict__ x)
{
    __shared__ float4 part[8][D4];
    const int b  = blockIdx.x;
    const int d4 = threadIdx.x & 31;
    const int g  = threadIdx.x >> 5;

    const float4* xb = x + (size_t)b * N * D4;

    float4 acc = make_float4(0.f, 0.f, 0.f, 0.f);
    #pragma unroll 4
    for (int n = g * 32; n < (g + 1) * 32; ++n) {
        float4 v = xb[n * D4 + d4];
        acc.x += v.x; acc.y += v.y; acc.z += v.z; acc.w += v.w;
    }
    part[g][d4] = acc;
    __syncthreads();

    if (g == 0) {
        float4 s = part[0][d4];
        #pragma unroll
        for (int k = 1; k < 8; ++k) {
            float4 v = part[k][d4];
            s.x += v.x; s.y += v.y; s.z += v.z; s.w += v.w;
        }
        g_sum[b * D4 + d4] = s;
    }
}

// Kernel 2: out[b,n,0:D] = x*(255/256); out[b,n,D:2D] = (S - x)/256
// One thread per float4 of x: total B*N*D4 = 65536 threads.
__global__ void write_kernel(const float4* __restrict__ x, float4* __restrict__ out)
{
    const int tid = blockIdx.x * blockDim.x + threadIdx.x;   // 0 .. B*N*D4-1
    if (tid >= B * N * D4) return;

    const int d4 = tid & (D4 - 1);
    const int bn = tid >> 5;            // b*N + n
    const int b  = bn >> 8;             // / N

    const float4 v = x[tid];
    const float4 s = g_sum[b * D4 + d4];

    const float c1 = 255.0f / 256.0f;
    const float c2 = 1.0f / 256.0f;

    float4 o1, o2;
    o1.x = v.x * c1; o1.y = v.y * c1; o1.z = v.z * c1; o1.w = v.w * c1;
    o2.x = (s.x - v.x) * c2; o2.y = (s.y - v.y) * c2;
    o2.z = (s.z - v.z) * c2; o2.w = (s.w - v.w) * c2;

    // out row layout: [B, N, 2D] -> row bn has 2*D4 float4s
    float4* orow = out + (size_t)bn * 2 * D4;
    orow[d4]      = o1;
    orow[D4 + d4] = o2;
}

extern "C" void kernel_launch(void* const* d_in, const int* in_sizes, int n_in,
                              void* d_out, int out_size)
{
    const float4* x = (const float4*)d_in[0];   // [B, N, D] fp32
    float4* out = (float4*)d_out;               // [B, N, 2D] fp32
    (void)in_sizes; (void)n_in; (void)out_size;

    reduce_kernel<<<B, 256>>>(x);
    write_kernel<<<(B * N * D4 + 255) / 256, 256>>>(x, out);
}

// round 3
// speedup vs baseline: 1.3527x; 1.3527x over previous
#include <cuda_runtime.h>

// Problem constants (fixed by reference setup_inputs)
#define B 8
#define N 256
#define D 128
#define D4 (D / 4)       // 32 float4 per feature row
#define CG 8             // column-groups per batch
#define CPB (D4 / CG)    // 4 float4 columns per block
#define NG 64            // node-groups (threads per column)
#define NPT (N / NG)     // 4 nodes per thread

__device__ __forceinline__ float4 f4add(float4 a, float4 b) {
    return make_float4(a.x + b.x, a.y + b.y, a.z + b.z, a.w + b.w);
}

// Single fused kernel.
// Grid: B*CG = 64 blocks. Block (b, cg) owns 4 float4 columns [cg*4, cg*4+4)
// of batch b — for BOTH the per-column sum S and the output write.
// Thread layout: c = tid & 3 (column within block, low bits for coalescing),
//                ng = tid >> 2 (node-group). Each thread handles nodes
//                n = ng + 64*k, k = 0..3, kept in registers.
__global__ void fused_kernel(const float4* __restrict__ x, float4* __restrict__ out)
{
    __shared__ float4 part[CPB][NG];

    const int blk = blockIdx.x;
    const int b   = blk >> 3;          // / CG
    const int cg  = blk & (CG - 1);
    const int cbase = cg * CPB;

    const int c  = threadIdx.x & (CPB - 1);
    const int ng = threadIdx.x >> 2;

    const int col = cbase + c;
    const float4* xb = x + (size_t)b * N * D4;

    // Load NPT nodes' float4 for this column, accumulate partial sum.
    float4 v[NPT];
    float4 acc = make_float4(0.f, 0.f, 0.f, 0.f);
    #pragma unroll
    for (int k = 0; k < NPT; ++k) {
        const int n = ng + NG * k;
        v[k] = xb[n * D4 + col];
        acc = f4add(acc, v[k]);
    }

    // Tree-reduce 64 node-group partials per column.
    part[c][ng] = acc;
    __syncthreads();
    if (ng < 16)
        part[c][ng] = f4add(f4add(part[c][ng],      part[c][ng + 16]),
                            f4add(part[c][ng + 32], part[c][ng + 48]));
    __syncthreads();
    if (ng < 4)
        part[c][ng] = f4add(f4add(part[c][ng],     part[c][ng + 4]),
                            f4add(part[c][ng + 8], part[c][ng + 12]));
    __syncthreads();
    if (ng == 0)
        part[c][0] = f4add(f4add(part[c][0], part[c][1]),
                           f4add(part[c][2], part[c][3]));
    __syncthreads();

    const float4 s = part[c][0];

    const float c1 = 255.0f / 256.0f;
    const float c2 = 1.0f / 256.0f;

    // Write both halves of the output row from retained registers.
    // out layout: [B, N, 2D] -> row (b*N + n) has 2*D4 float4s.
    #pragma unroll
    for (int k = 0; k < NPT; ++k) {
        const int n = ng + NG * k;
        float4* orow = out + ((size_t)(b * N + n)) * (2 * D4);

        float4 o1, o2;
        o1.x = v[k].x * c1; o1.y = v[k].y * c1;
        o1.z = v[k].z * c1; o1.w = v[k].w * c1;
        o2.x = (s.x - v[k].x) * c2; o2.y = (s.y - v[k].y) * c2;
        o2.z = (s.z - v[k].z) * c2; o2.w = (s.w - v[k].w) * c2;

        orow[col]      = o1;
        orow[D4 + col] = o2;
    }
}

extern "C" void kernel_launch(void* const* d_in, const int* in_sizes, int n_in,
                              void* d_out, int out_size)
{
    const float4* x = (const float4*)d_in[0];   // [B, N, D] fp32
    float4* out = (float4*)d_out;               // [B, N, 2D] fp32
    (void)in_sizes; (void)n_in; (void)out_size;

    fused_kernel<<<B * CG, NG * CPB>>>(x, out);
}

// round 5
// speedup vs baseline: 1.4070x; 1.0402x over previous
#include <cuda_runtime.h>

// Problem constants (fixed by reference setup_inputs)
#define B 8
#define N 256
#define D 128
#define D4 (D / 4)       // 32 float4 per feature row
#define CG 8             // column-groups per batch (grid = B*CG = 64 blocks)
#define CPB (D4 / CG)    // 4 float4 columns per block
#define NGS 64           // node-groups (threads per column)
#define NPT (N / NGS)    // 4 nodes per thread

__device__ __forceinline__ float4 f4add(float4 a, float4 b) {
    return make_float4(a.x + b.x, a.y + b.y, a.z + b.z, a.w + b.w);
}

// Single fused kernel, one __syncthreads.
// Block (b, cg) owns 4 float4 columns of batch b.
// Thread layout: c = tid&3 (column, low bits -> 64B coalesced chunks),
//                ng = tid>>2. Warp w holds ngs [8w, 8w+8).
// Path: load 4 nodes -> store first output half immediately (independent of S)
//       -> warp butterfly over ng -> 512B smem -> 1 barrier -> cross-warp sum
//       -> store second half.
__global__ void __launch_bounds__(256, 1)
fused_kernel(const float4* __restrict__ x, float4* __restrict__ out)
{
    __shared__ float4 part[8][CPB];   // [warp][col-in-block]

    const int blk = blockIdx.x;
    const int b   = blk >> 3;
    const int cg  = blk & (CG - 1);

    const int c    = threadIdx.x & (CPB - 1);
    const int ng   = threadIdx.x >> 2;
    const int lane = threadIdx.x & 31;
    const int w    = threadIdx.x >> 5;
    const int col  = cg * CPB + c;

    const float4* xb = x + (size_t)b * N * D4;

    // Load NPT nodes for this column; accumulate partial sum.
    float4 v[NPT];
    float4 acc = make_float4(0.f, 0.f, 0.f, 0.f);
    #pragma unroll
    for (int k = 0; k < NPT; ++k) {
        const int n = ng + NGS * k;
        v[k] = xb[n * D4 + col];
        acc = f4add(acc, v[k]);
    }

    const float c1 = 255.0f / 256.0f;
    const float c2 = 1.0f / 256.0f;

    // First half of output does NOT depend on the sum — drain it now,
    // overlapping the writes with the reduction below.
    #pragma unroll
    for (int k = 0; k < NPT; ++k) {
        const int n = ng + NGS * k;
        float4 o1;
        o1.x = v[k].x * c1; o1.y = v[k].y * c1;
        o1.z = v[k].z * c1; o1.w = v[k].w * c1;
        out[((size_t)(b * N + n)) * (2 * D4) + col] = o1;
    }

    // Warp-level butterfly over the 8 node-groups inside this warp
    // (lanes differing in bits 2..4 share column c).
    #pragma unroll
    for (int m = 4; m < 32; m <<= 1) {
        acc.x += __shfl_xor_sync(0xffffffffu, acc.x, m);
        acc.y += __shfl_xor_sync(0xffffffffu, acc.y, m);
        acc.z += __shfl_xor_sync(0xffffffffu, acc.z, m);
        acc.w += __shfl_xor_sync(0xffffffffu, acc.w, m);
    }
    if (lane < CPB) part[w][c] = acc;     // lanes 0..3 carry c = 0..3
    __syncthreads();

    // Cross-warp combine: 8 broadcast LDS.128 + adds.
    float4 s = part[0][c];
    #pragma unroll
    for (int ww = 1; ww < 8; ++ww) s = f4add(s, part[ww][c]);

    // Second half: (S - x) / N
    #pragma unroll
    for (int k = 0; k < NPT; ++k) {
        const int n = ng + NGS * k;
        float4 o2;
        o2.x = (s.x - v[k].x) * c2; o2.y = (s.y - v[k].y) * c2;
        o2.z = (s.z - v[k].z) * c2; o2.w = (s.w - v[k].w) * c2;
        out[((size_t)(b * N + n)) * (2 * D4) + D4 + col] = o2;
    }
}

extern "C" void kernel_launch(void* const* d_in, const int* in_sizes, int n_in,
                              void* d_out, int out_size)
{
    const float4* x = (const float4*)d_in[0];   // [B, N, D] fp32
    float4* out = (float4*)d_out;               // [B, N, 2D] fp32
    (void)in_sizes; (void)n_in; (void)out_size;

    fused_kernel<<<B * CG, NGS * CPB>>>(x, out);
}